// round 12
// baseline (speedup 1.0000x reference)
#include <cuda_runtime.h>
#include <cuda_fp16.h>
#include <cstdint>

// ---------------- problem constants ----------------
#define DD   44          // DESIZE
#define HH   48
#define WW   48
#define DHW  (DD*HH*WW)  // 101376 = FLAT
#define NB   4           // batch
#define N1   1024
#define N2   128
#define N3   10
#define NT   216         // 6*6*6 taps
#define NP   108         // tap pairs
#define CONVEY 0.9f

// tile geometry for k_step
#define TX 16
#define TY 16
#define HX 21            // TX + 5
#define HY 21
#define HZ 6
#define HXE 11           // even window positions 0,2,..,20
#define HXO 10           // odd positions 1,3,..,19
#define TILE_ELEMS (HZ*HY*HX)   // 2646
#define NSTEPBLK (3*3*DD)       // 396 blocks, 256 voxels each

// ---------------- device scratch (no allocation allowed) ----------------
__device__ float4 g_neuA[DHW];
__device__ float4 g_neuB[DHW];
__device__ __align__(16) __half2 g_synTh[(size_t)NP * DHW]; // [pair][permvox] fp16 (43.8MB)
__device__ float  g_acc1[NB * N1];
__device__ float  g_acc2[NB * N2];

// ---------------- packed fp32x2 helpers (Blackwell) ----------------
__device__ __forceinline__ unsigned long long pack2(float w) {
    unsigned long long r;
    asm("mov.b64 %0, {%1, %1};" : "=l"(r) : "f"(w));
    return r;
}
__device__ __forceinline__ void ffma2(unsigned long long& acc,
                                      unsigned long long a,
                                      unsigned long long b) {
    asm("fma.rn.f32x2 %0, %1, %2, %0;" : "+l"(acc) : "l"(a), "l"(b));
}
__device__ __forceinline__ unsigned long long add2(unsigned long long a,
                                                   unsigned long long b) {
    unsigned long long r;
    asm("add.rn.f32x2 %0, %1, %2;" : "=l"(r) : "l"(a), "l"(b));
    return r;
}
__device__ __forceinline__ float2 unpack2(unsigned long long v) {
    float2 f;
    asm("mov.b64 {%0, %1}, %2;" : "=f"(f.x), "=f"(f.y) : "l"(v));
    return f;
}

// ---------------- cp.async helpers ----------------
__device__ __forceinline__ void cp_async16(void* smem_dst, const void* gsrc) {
    unsigned saddr = (unsigned)__cvta_generic_to_shared(smem_dst);
    asm volatile("cp.async.cg.shared.global [%0], [%1], 16;" :: "r"(saddr), "l"(gsrc));
}
#define CP_COMMIT() asm volatile("cp.async.commit_group;" ::: "memory")
#define CP_WAIT(n)  asm volatile("cp.async.wait_group %0;" :: "n"(n) : "memory")

// ---------------- kernel 1: neu = vinput + frame, batch-packed ----------------
__global__ void __launch_bounds__(256) k_init_neu(const float* __restrict__ vin,
                                                  const float* __restrict__ frame) {
    int v = blockIdx.x * 256 + threadIdx.x;
    if (v >= DHW) return;
    float f = frame[v];
    float4 o;
    o.x = vin[0 * DHW + v] + f;
    o.y = vin[1 * DHW + v] + f;
    o.z = vin[2 * DHW + v] + f;
    o.w = vin[3 * DHW + v] + f;
    g_neuA[v] = o;
}

// ---------------- kernel 1b: transpose synapse [vox][tap] -> fp16 [pair][permvox]
__global__ void __launch_bounds__(256) k_transpose(const float* __restrict__ syn) {
    __shared__ float sm[32 * 217];
    const int b  = blockIdx.x;       // 0..3167
    const int sb = b >> 3;           // step block 0..395
    const int w  = b & 7;            // warp-chunk 0..7
    const int bx = sb % 3;
    const int tq = sb / 3;
    const int by = tq % 3;
    const int z  = tq / 3;
    const int x0 = bx * TX, y0 = by * TY;
    const int t  = threadIdx.x;

    const size_t base0 = ((size_t)z * (HH*WW) + (size_t)(y0 + 2*w    ) * WW + x0) * NT;
    const size_t base1 = ((size_t)z * (HH*WW) + (size_t)(y0 + 2*w + 1) * WW + x0) * NT;

#pragma unroll
    for (int i = 0; i < 27; ++i) {          // 27*256 = 6912 = 32*216
        int idx    = i * 256 + t;
        int chunk  = idx / 3456;
        int within = idx - chunk * 3456;
        int vl     = within / NT;            // 0..15
        int tap    = within - vl * NT;
        float val  = syn[(chunk ? base1 : base0) + within];
        sm[(chunk * 16 + vl) * 217 + tap] = val;
    }
    __syncthreads();

    const int lane = t & 31;
    const int prow = t >> 5;                 // 0..7
    const size_t obase = (size_t)sb * 256 + w * 32 + lane;
#pragma unroll
    for (int p = prow; p < NP; p += 8) {
        float w0 = sm[lane * 217 + 2 * p];
        float w1 = sm[lane * 217 + 2 * p + 1];
        g_synTh[(size_t)p * DHW + obase] = __floats2half2_rn(w0, w1);
    }
}

// ---------------- kernel 2: locally-connected step, 4-way tap split, 512 thr --
// Pair slot s (0..127) = warp*8 + (lane&7): output voxels x = x0+2*(s&7){,+1}
// at row ty = s>>3 (== warp). Four hemi-threads per slot (h = (lane>>3)&3),
// h handles (dz,dy) rows R = 9h..9h+8 of 36. Partials combined with
// shfl.xor(8) + shfl.xor(16); lanes h<2 store voxel v0 / v0+1.
__global__ void __launch_bounds__(512) k_step(int dir) {
    __shared__ float4 tileE[HZ * HY * HXE];   // even local-x positions
    __shared__ float4 tileO[HZ * HY * HXO];   // odd  local-x positions

    const int sb = blockIdx.x;               // 0..395
    const int bx = sb % 3;
    const int tq = sb / 3;
    const int by = tq % 3;
    const int z  = tq / 3;
    const int x0 = bx * TX, y0 = by * TY;
    const int t    = threadIdx.x;
    const int lane = t & 31;
    const int warp = t >> 5;                  // 0..15
    const int s    = warp * 8 + (lane & 7);   // pair slot 0..127
    const int h    = (lane >> 3) & 3;         // tap quarter 0..3
    const int txp  = s & 7;
    const int ty   = s >> 3;                  // == warp

    const float4* __restrict__ src = dir ? g_neuB : g_neuA;
    float4*       __restrict__ dst = dir ? g_neuA : g_neuB;

    // load halo tile (zeros outside the volume)
#pragma unroll
    for (int i = 0; i < 6; ++i) {
        int idx = i * 512 + t;
        if (idx < TILE_ELEMS) {
            int lp = idx % HX;
            int r  = idx / HX;
            int ly = r % HY;
            int lz = r / HY;
            int gx = x0 + lp - 3, gy = y0 + ly - 3, gz = z + lz - 3;
            float4 v = make_float4(0.f, 0.f, 0.f, 0.f);
            if ((unsigned)gx < (unsigned)WW && (unsigned)gy < (unsigned)HH &&
                (unsigned)gz < (unsigned)DD)
                v = src[((size_t)gz * HH + gy) * WW + gx];
            if (lp & 1) tileO[(lz * HY + ly) * HXO + (lp >> 1)] = v;
            else        tileE[(lz * HY + ly) * HXE + (lp >> 1)] = v;
        }
    }
    __syncthreads();

    const int v0 = 2 * s;
    const char* wbase = reinterpret_cast<const char*>(g_synTh + ((size_t)sb * 256 + v0));
    const size_t pb0 = (size_t)h * 27 * DHW;   // R = 9h -> pb = R*3*DHW

    const ulonglong2* tE = reinterpret_cast<const ulonglong2*>(tileE);
    const ulonglong2* tO = reinterpret_cast<const ulonglong2*>(tileO);

    unsigned long long a0 = 0ull, a1 = 0ull;  // voxel v0: (b0,b1), (b2,b3)
    unsigned long long c0 = 0ull, c1 = 0ull;  // voxel v0+1

    // weight loader for local row r (global row R = 9h + r), 3 uint2 per row
    auto ldw = [&](int r, uint2& A, uint2& B, uint2& C) {
        const size_t pb = pb0 + (size_t)(3 * r) * DHW;
        A = *reinterpret_cast<const uint2*>(wbase + pb * 4);
        B = *reinterpret_cast<const uint2*>(wbase + (pb + (size_t)DHW) * 4);
        C = *reinterpret_cast<const uint2*>(wbase + (pb + (size_t)(2 * DHW)) * 4);
    };

    // depth-3 prefetch ring
    uint2 WA[3], WB[3], WC[3];
#pragma unroll
    for (int r = 0; r < 3; ++r) ldw(r, WA[r], WB[r], WC[r]);

#pragma unroll
    for (int r = 0; r < 9; ++r) {
        const int sl = r % 3;
        uint2 wA = WA[sl];
        uint2 wB = WB[sl];
        uint2 wC = WC[sl];
        if (r + 3 < 9) ldw(r + 3, WA[sl], WB[sl], WC[sl]);

        const int R   = h * 9 + r;            // global (dz,dy) row
        const int dz  = R / 6;
        const int dy  = R - dz * 6;
        const int row = dz * HY + ty + dy;
        const ulonglong2* rE = tE + row * HXE + txp;
        const ulonglong2* rO = tO + row * HXO + txp;
        ulonglong2 n0 = rE[0];
        ulonglong2 n1 = rO[0];
        ulonglong2 n2 = rE[1];
        ulonglong2 n3 = rO[1];
        ulonglong2 n4 = rE[2];
        ulonglong2 n5 = rO[2];
        ulonglong2 n6 = rE[3];

#pragma unroll
        for (int q = 0; q < 3; ++q) {
            uint2 u = (q == 0) ? wA : (q == 1) ? wB : wC;
            float2 fa = __half22float2(*reinterpret_cast<__half2*>(&u.x));
            float2 fb = __half22float2(*reinterpret_cast<__half2*>(&u.y));
            unsigned long long wax = pack2(fa.x), way = pack2(fa.y);
            unsigned long long wbx = pack2(fb.x), wby = pack2(fb.y);
            const ulonglong2* m0 = (q == 0) ? &n0 : (q == 1) ? &n2 : &n4;
            const ulonglong2* m1 = (q == 0) ? &n1 : (q == 1) ? &n3 : &n5;
            const ulonglong2* m2 = (q == 0) ? &n2 : (q == 1) ? &n4 : &n6;
            ffma2(a0, m0->x, wax); ffma2(a1, m0->y, wax);
            ffma2(a0, m1->x, way); ffma2(a1, m1->y, way);
            ffma2(c0, m1->x, wbx); ffma2(c1, m1->y, wbx);
            ffma2(c0, m2->x, wby); ffma2(c1, m2->y, wby);
        }
    }

    // combine 4 quarters within the warp (partners lane^8, lane^16)
    a0 = add2(a0, __shfl_xor_sync(0xFFFFFFFFu, a0, 8));
    a1 = add2(a1, __shfl_xor_sync(0xFFFFFFFFu, a1, 8));
    c0 = add2(c0, __shfl_xor_sync(0xFFFFFFFFu, c0, 8));
    c1 = add2(c1, __shfl_xor_sync(0xFFFFFFFFu, c1, 8));
    a0 = add2(a0, __shfl_xor_sync(0xFFFFFFFFu, a0, 16));
    a1 = add2(a1, __shfl_xor_sync(0xFFFFFFFFu, a1, 16));
    c0 = add2(c0, __shfl_xor_sync(0xFFFFFFFFu, c0, 16));
    c1 = add2(c1, __shfl_xor_sync(0xFFFFFFFFu, c1, 16));

    if (h < 2) {
        unsigned long long o0 = h ? c0 : a0;
        unsigned long long o1 = h ? c1 : a1;
        float2 r0 = unpack2(o0), r1 = unpack2(o1);
        float4 o;
        o.x = fmaxf(r0.x, 0.f) * CONVEY;
        o.y = fmaxf(r0.y, 0.f) * CONVEY;
        o.z = fmaxf(r1.x, 0.f) * CONVEY;
        o.w = fmaxf(r1.y, 0.f) * CONVEY;
        size_t obase = ((size_t)z * HH + (y0 + ty)) * WW + (x0 + 2 * txp);
        dst[obase + h] = o;
    }
}

// ---------------- kernel 3: bias-initialize accumulators (every launch!) ------
__global__ void __launch_bounds__(256) k_init_acc(const float* __restrict__ b1,
                                                  const float* __restrict__ b2) {
    int i = blockIdx.x * 256 + threadIdx.x;
    if (i < NB * N1) g_acc1[i] = b1[i & (N1 - 1)];
    if (i < NB * N2) g_acc2[i] = b2[i & (N2 - 1)];
}

// ---------------- kernel 4: FC1 split-K via cp.async deep pipeline ------------
#define KSPLIT  576
#define ROWSPB  176   // 576 * 176 == 101376 exactly
#define GSTAGES 12
__global__ void __launch_bounds__(256) k_gemm1(const float* __restrict__ W1) {
    __shared__ float4 swb[GSTAGES][256];   // 48KB ring
    __shared__ float4 sx[ROWSPB];
    const int f0  = blockIdx.x * ROWSPB;
    const int tid = threadIdx.x;

    if (tid < ROWSPB) sx[tid] = g_neuB[f0 + tid];

    const char* gbase = reinterpret_cast<const char*>(W1)
                      + ((size_t)f0 * N1 + tid * 4) * 4;

    // prologue: stages 0..10 in flight
#pragma unroll
    for (int s = 0; s < GSTAGES - 1; ++s) {
        cp_async16(&swb[s][tid], gbase + (size_t)s * (N1 * 4));
        CP_COMMIT();
    }
    __syncthreads();   // sx visibility

    const int j0 = tid * 4;
    float a00=0,a01=0,a02=0,a03=0;
    float a10=0,a11=0,a12=0,a13=0;
    float a20=0,a21=0,a22=0,a23=0;
    float a30=0,a31=0,a32=0,a33=0;

#pragma unroll 12
    for (int i = 0; i < ROWSPB; ++i) {
        CP_WAIT(GSTAGES - 2);                 // row i ready (own 16B slot)
        float4 w  = swb[i % GSTAGES][tid];
        float4 xv = sx[i];
        a00 += xv.x * w.x; a01 += xv.x * w.y; a02 += xv.x * w.z; a03 += xv.x * w.w;
        a10 += xv.y * w.x; a11 += xv.y * w.y; a12 += xv.y * w.z; a13 += xv.y * w.w;
        a20 += xv.z * w.x; a21 += xv.z * w.y; a22 += xv.z * w.z; a23 += xv.z * w.w;
        a30 += xv.w * w.x; a31 += xv.w * w.y; a32 += xv.w * w.z; a33 += xv.w * w.w;
        if (i + GSTAGES - 1 < ROWSPB)
            cp_async16(&swb[(i + GSTAGES - 1) % GSTAGES][tid],
                       gbase + (size_t)(i + GSTAGES - 1) * (N1 * 4));
        CP_COMMIT();                          // keep group counting aligned
    }

    atomicAdd(&g_acc1[0 * N1 + j0 + 0], a00); atomicAdd(&g_acc1[0 * N1 + j0 + 1], a01);
    atomicAdd(&g_acc1[0 * N1 + j0 + 2], a02); atomicAdd(&g_acc1[0 * N1 + j0 + 3], a03);
    atomicAdd(&g_acc1[1 * N1 + j0 + 0], a10); atomicAdd(&g_acc1[1 * N1 + j0 + 1], a11);
    atomicAdd(&g_acc1[1 * N1 + j0 + 2], a12); atomicAdd(&g_acc1[1 * N1 + j0 + 3], a13);
    atomicAdd(&g_acc1[2 * N1 + j0 + 0], a20); atomicAdd(&g_acc1[2 * N1 + j0 + 1], a21);
    atomicAdd(&g_acc1[2 * N1 + j0 + 2], a22); atomicAdd(&g_acc1[2 * N1 + j0 + 3], a23);
    atomicAdd(&g_acc1[3 * N1 + j0 + 0], a30); atomicAdd(&g_acc1[3 * N1 + j0 + 1], a31);
    atomicAdd(&g_acc1[3 * N1 + j0 + 2], a32); atomicAdd(&g_acc1[3 * N1 + j0 + 3], a33);
}

// ---------------- kernel 5: FC2 (relu(acc1) @ W2), atomics into g_acc2 --------
__global__ void __launch_bounds__(128) k_gemm2(const float* __restrict__ W2) {
    const int t     = threadIdx.x;
    const int jbase = blockIdx.x * 64;
    float acc0 = 0, acc1 = 0, acc2 = 0, acc3 = 0;
#pragma unroll 4
    for (int j = 0; j < 64; ++j) {
        int jj  = jbase + j;
        float w = W2[(size_t)jj * N2 + t];
        acc0 += fmaxf(g_acc1[0 * N1 + jj], 0.f) * w;
        acc1 += fmaxf(g_acc1[1 * N1 + jj], 0.f) * w;
        acc2 += fmaxf(g_acc1[2 * N1 + jj], 0.f) * w;
        acc3 += fmaxf(g_acc1[3 * N1 + jj], 0.f) * w;
    }
    atomicAdd(&g_acc2[0 * N2 + t], acc0);
    atomicAdd(&g_acc2[1 * N2 + t], acc1);
    atomicAdd(&g_acc2[2 * N2 + t], acc2);
    atomicAdd(&g_acc2[3 * N2 + t], acc3);
}

// ---------------- kernel 6: FC3 -> output logits ----------------
__global__ void __launch_bounds__(64) k_fc3(const float* __restrict__ W3,
                                            const float* __restrict__ b3,
                                            float* __restrict__ out) {
    int t = threadIdx.x;
    if (t >= NB * N3) return;
    int b = t / N3, o = t % N3;
    float s = b3[o];
#pragma unroll 8
    for (int k = 0; k < N2; ++k)
        s += fmaxf(g_acc2[b * N2 + k], 0.f) * W3[k * N3 + o];
    out[b * N3 + o] = s;
}

// ---------------- launch ----------------
extern "C" void kernel_launch(void* const* d_in, const int* in_sizes, int n_in,
                              void* d_out, int out_size) {
    const float* vin   = (const float*)d_in[0];
    const float* frame = (const float*)d_in[1];
    const float* syn   = (const float*)d_in[2];
    const float* W1    = (const float*)d_in[3];
    const float* b1    = (const float*)d_in[4];
    const float* W2    = (const float*)d_in[5];
    const float* b2    = (const float*)d_in[6];
    const float* W3    = (const float*)d_in[7];
    const float* b3    = (const float*)d_in[8];
    float* out = (float*)d_out;

    k_init_neu<<<DHW / 256, 256>>>(vin, frame);
    k_transpose<<<NSTEPBLK * 8, 256>>>(syn);

    k_step<<<NSTEPBLK, 512>>>(0);   // A -> B
    k_step<<<NSTEPBLK, 512>>>(1);   // B -> A
    k_step<<<NSTEPBLK, 512>>>(0);   // A -> B
    k_step<<<NSTEPBLK, 512>>>(1);   // B -> A
    k_step<<<NSTEPBLK, 512>>>(0);   // A -> B  (final state in g_neuB)

    k_init_acc<<<18, 256>>>(b1, b2);
    k_gemm1<<<KSPLIT, 256>>>(W1);
    k_gemm2<<<16, 128>>>(W2);
    k_fc3<<<1, 64>>>(W3, b3, out);
}

// round 13
// speedup vs baseline: 1.0641x; 1.0641x over previous
#include <cuda_runtime.h>
#include <cuda_fp16.h>
#include <cstdint>

// ---------------- problem constants ----------------
#define DD   44          // DESIZE
#define HH   48
#define WW   48
#define DHW  (DD*HH*WW)  // 101376 = FLAT
#define NB   4           // batch
#define N1   1024
#define N2   128
#define N3   10
#define NT   216         // 6*6*6 taps
#define NP   108         // tap pairs
#define CONVEY 0.9f

// tile geometry for k_step
#define TX 16
#define TY 16
#define HX 21            // TX + 5
#define HY 21
#define HZ 6
#define HXE 11           // even window positions 0,2,..,20
#define HXO 10           // odd positions 1,3,..,19
#define TILE_ELEMS (HZ*HY*HX)   // 2646
#define NSTEPBLK (3*3*DD)       // 396 blocks, 256 voxels each

// ---------------- device scratch (no allocation allowed) ----------------
__device__ float4 g_neuA[DHW];
__device__ float4 g_neuB[DHW];
__device__ __align__(16) __half2 g_synTh[(size_t)NP * DHW]; // [pair][permvox] fp16 (43.8MB)
__device__ float  g_acc1[NB * N1];
__device__ float  g_acc2[NB * N2];

// ---------------- packed fp32x2 helpers (Blackwell) ----------------
__device__ __forceinline__ unsigned long long pack2(float w) {
    unsigned long long r;
    asm("mov.b64 %0, {%1, %1};" : "=l"(r) : "f"(w));
    return r;
}
__device__ __forceinline__ void ffma2(unsigned long long& acc,
                                      unsigned long long a,
                                      unsigned long long b) {
    asm("fma.rn.f32x2 %0, %1, %2, %0;" : "+l"(acc) : "l"(a), "l"(b));
}
__device__ __forceinline__ unsigned long long add2(unsigned long long a,
                                                   unsigned long long b) {
    unsigned long long r;
    asm("add.rn.f32x2 %0, %1, %2;" : "=l"(r) : "l"(a), "l"(b));
    return r;
}
__device__ __forceinline__ float2 unpack2(unsigned long long v) {
    float2 f;
    asm("mov.b64 {%0, %1}, %2;" : "=f"(f.x), "=f"(f.y) : "l"(v));
    return f;
}

// ---------------- cp.async helpers ----------------
__device__ __forceinline__ void cp_async16(void* smem_dst, const void* gsrc) {
    unsigned saddr = (unsigned)__cvta_generic_to_shared(smem_dst);
    asm volatile("cp.async.cg.shared.global [%0], [%1], 16;" :: "r"(saddr), "l"(gsrc));
}
#define CP_COMMIT() asm volatile("cp.async.commit_group;" ::: "memory")
#define CP_WAIT(n)  asm volatile("cp.async.wait_group %0;" :: "n"(n) : "memory")

// ---------------- kernel 1: neu = vinput + frame, batch-packed ----------------
__global__ void __launch_bounds__(256) k_init_neu(const float* __restrict__ vin,
                                                  const float* __restrict__ frame) {
    int v = blockIdx.x * 256 + threadIdx.x;
    if (v >= DHW) return;
    float f = frame[v];
    float4 o;
    o.x = vin[0 * DHW + v] + f;
    o.y = vin[1 * DHW + v] + f;
    o.z = vin[2 * DHW + v] + f;
    o.w = vin[3 * DHW + v] + f;
    g_neuA[v] = o;
}

// ---------------- kernel 1b: transpose synapse [vox][tap] -> fp16 [pair][permvox]
__global__ void __launch_bounds__(256) k_transpose(const float* __restrict__ syn) {
    __shared__ float sm[32 * 217];
    const int b  = blockIdx.x;       // 0..3167
    const int sb = b >> 3;           // step block 0..395
    const int w  = b & 7;            // warp-chunk 0..7
    const int bx = sb % 3;
    const int tq = sb / 3;
    const int by = tq % 3;
    const int z  = tq / 3;
    const int x0 = bx * TX, y0 = by * TY;
    const int t  = threadIdx.x;

    const size_t base0 = ((size_t)z * (HH*WW) + (size_t)(y0 + 2*w    ) * WW + x0) * NT;
    const size_t base1 = ((size_t)z * (HH*WW) + (size_t)(y0 + 2*w + 1) * WW + x0) * NT;

#pragma unroll
    for (int i = 0; i < 27; ++i) {          // 27*256 = 6912 = 32*216
        int idx    = i * 256 + t;
        int chunk  = idx / 3456;
        int within = idx - chunk * 3456;
        int vl     = within / NT;            // 0..15
        int tap    = within - vl * NT;
        float val  = syn[(chunk ? base1 : base0) + within];
        sm[(chunk * 16 + vl) * 217 + tap] = val;
    }
    __syncthreads();

    const int lane = t & 31;
    const int prow = t >> 5;                 // 0..7
    const size_t obase = (size_t)sb * 256 + w * 32 + lane;
#pragma unroll
    for (int p = prow; p < NP; p += 8) {
        float w0 = sm[lane * 217 + 2 * p];
        float w1 = sm[lane * 217 + 2 * p + 1];
        g_synTh[(size_t)p * DHW + obase] = __floats2half2_rn(w0, w1);
    }
}

// ---------------- kernel 2: locally-connected step, x-quad, 128 threads -------
// Quad slot s (0..63): voxels x = x0 + 4*(s&3) + j (j=0..3) at row ty = s>>2.
// Two hemi-threads per slot in the SAME warp (lane^16): h=0 -> dz 0..2,
// h=1 -> dz 3..5. Per (dz,dy) row: 9 LDS.128 feed 24 voxel-taps; weights for a
// tap pair x 4 voxels come as one LDG.128. Partials combined via shfl.xor(16);
// h=0 stores voxels 0,1; h=1 stores voxels 2,3.
__global__ void __launch_bounds__(128) k_step(int dir) {
    __shared__ float4 tileE[HZ * HY * HXE];   // even local-x positions
    __shared__ float4 tileO[HZ * HY * HXO];   // odd  local-x positions

    const int sb = blockIdx.x;               // 0..395
    const int bx = sb % 3;
    const int tq = sb / 3;
    const int by = tq % 3;
    const int z  = tq / 3;
    const int x0 = bx * TX, y0 = by * TY;
    const int t    = threadIdx.x;
    const int lane = t & 31;
    const int warp = t >> 5;                  // 0..3
    const int s    = warp * 16 + (lane & 15); // quad slot 0..63
    const int h    = lane >> 4;               // tap hemisphere 0/1
    const int qx   = s & 3;                   // x quad 0..3
    const int ty   = s >> 2;                  // 0..15

    const float4* __restrict__ src = dir ? g_neuB : g_neuA;
    float4*       __restrict__ dst = dir ? g_neuA : g_neuB;

    // load halo tile (zeros outside the volume)
#pragma unroll
    for (int i = 0; i < 21; ++i) {
        int idx = i * 128 + t;
        if (idx < TILE_ELEMS) {
            int lp = idx % HX;
            int r  = idx / HX;
            int ly = r % HY;
            int lz = r / HY;
            int gx = x0 + lp - 3, gy = y0 + ly - 3, gz = z + lz - 3;
            float4 v = make_float4(0.f, 0.f, 0.f, 0.f);
            if ((unsigned)gx < (unsigned)WW && (unsigned)gy < (unsigned)HH &&
                (unsigned)gz < (unsigned)DD)
                v = src[((size_t)gz * HH + gy) * WW + gx];
            if (lp & 1) tileO[(lz * HY + ly) * HXO + (lp >> 1)] = v;
            else        tileE[(lz * HY + ly) * HXE + (lp >> 1)] = v;
        }
    }
    __syncthreads();

    const int v0 = ty * 16 + 4 * qx;          // first voxel of the quad
    const char* wbase = reinterpret_cast<const char*>(g_synTh + ((size_t)sb * 256 + v0));

    const ulonglong2* tE = reinterpret_cast<const ulonglong2*>(tileE);
    const ulonglong2* tO = reinterpret_cast<const ulonglong2*>(tileO);

    // accumulators: voxel j -> (batch01, batch23)
    unsigned long long A0a = 0ull, A0b = 0ull;
    unsigned long long A1a = 0ull, A1b = 0ull;
    unsigned long long A2a = 0ull, A2b = 0ull;
    unsigned long long A3a = 0ull, A3b = 0ull;

    // weight loader for hemisphere row r (dz = h*3 + r/6, dy = r%6):
    // 3 tap-pairs x 4 voxels = 3 uint4
    auto ldw = [&](int r, uint4& U0, uint4& U1, uint4& U2) {
        const int dz = h * 3 + r / 6;
        const int dy = r % 6;
        const size_t pb = (size_t)(dz * 18 + dy * 3) * DHW;
        U0 = *reinterpret_cast<const uint4*>(wbase + pb * 4);
        U1 = *reinterpret_cast<const uint4*>(wbase + (pb + (size_t)DHW) * 4);
        U2 = *reinterpret_cast<const uint4*>(wbase + (pb + (size_t)(2 * DHW)) * 4);
    };

    // depth-2 prefetch ring
    uint4 P0a, P0b, P0c, P1a, P1b, P1c;
    ldw(0, P0a, P0b, P0c);
    ldw(1, P1a, P1b, P1c);

#pragma unroll
    for (int r = 0; r < 18; ++r) {
        uint4 W0 = (r & 1) ? P1a : P0a;
        uint4 W1 = (r & 1) ? P1b : P0b;
        uint4 W2 = (r & 1) ? P1c : P0c;
        if (r + 2 < 18) {
            if (r & 1) ldw(r + 2, P1a, P1b, P1c);
            else       ldw(r + 2, P0a, P0b, P0c);
        }

        const int dz  = h * 3 + r / 6;
        const int dy  = r % 6;
        const int row = dz * HY + ty + dy;
        const ulonglong2* rE = tE + row * HXE + 2 * qx;
        const ulonglong2* rO = tO + row * HXO + 2 * qx;
        ulonglong2 e0 = rE[0];
        ulonglong2 e1 = rE[1];
        ulonglong2 e2 = rE[2];
        ulonglong2 e3 = rE[3];
        ulonglong2 e4 = rE[4];
        ulonglong2 o0 = rO[0];
        ulonglong2 o1 = rO[1];
        ulonglong2 o2 = rO[2];
        ulonglong2 o3 = rO[3];

#pragma unroll
        for (int q = 0; q < 3; ++q) {
            uint4 u = (q == 0) ? W0 : (q == 1) ? W1 : W2;
            // component j of u = (tap 2q, tap 2q+1) weights for voxel j
            float2 f0 = __half22float2(*reinterpret_cast<__half2*>(&u.x));
            float2 f1 = __half22float2(*reinterpret_cast<__half2*>(&u.y));
            float2 f2 = __half22float2(*reinterpret_cast<__half2*>(&u.z));
            float2 f3 = __half22float2(*reinterpret_cast<__half2*>(&u.w));
            const ulonglong2* nq0 = (q == 0) ? &e0 : (q == 1) ? &e1 : &e2;  // E[q]
            const ulonglong2* nq1 = (q == 0) ? &o0 : (q == 1) ? &o1 : &o2;  // O[q]
            const ulonglong2* nq2 = (q == 0) ? &e1 : (q == 1) ? &e2 : &e3;  // E[q+1]
            const ulonglong2* nq3 = (q == 0) ? &o1 : (q == 1) ? &o2 : &o3;  // O[q+1]
            const ulonglong2* nq4 = (q == 0) ? &e2 : (q == 1) ? &e3 : &e4;  // E[q+2]

            unsigned long long w;
            // voxel 0: taps 2q -> E[q], 2q+1 -> O[q]
            w = pack2(f0.x); ffma2(A0a, nq0->x, w); ffma2(A0b, nq0->y, w);
            w = pack2(f0.y); ffma2(A0a, nq1->x, w); ffma2(A0b, nq1->y, w);
            // voxel 1: taps 2q -> O[q], 2q+1 -> E[q+1]
            w = pack2(f1.x); ffma2(A1a, nq1->x, w); ffma2(A1b, nq1->y, w);
            w = pack2(f1.y); ffma2(A1a, nq2->x, w); ffma2(A1b, nq2->y, w);
            // voxel 2: taps 2q -> E[q+1], 2q+1 -> O[q+1]
            w = pack2(f2.x); ffma2(A2a, nq2->x, w); ffma2(A2b, nq2->y, w);
            w = pack2(f2.y); ffma2(A2a, nq3->x, w); ffma2(A2b, nq3->y, w);
            // voxel 3: taps 2q -> O[q+1], 2q+1 -> E[q+2]
            w = pack2(f3.x); ffma2(A3a, nq3->x, w); ffma2(A3b, nq3->y, w);
            w = pack2(f3.y); ffma2(A3a, nq4->x, w); ffma2(A3b, nq4->y, w);
        }
    }

    // combine hemispheres (partner = lane ^ 16)
    A0a = add2(A0a, __shfl_xor_sync(0xFFFFFFFFu, A0a, 16));
    A0b = add2(A0b, __shfl_xor_sync(0xFFFFFFFFu, A0b, 16));
    A1a = add2(A1a, __shfl_xor_sync(0xFFFFFFFFu, A1a, 16));
    A1b = add2(A1b, __shfl_xor_sync(0xFFFFFFFFu, A1b, 16));
    A2a = add2(A2a, __shfl_xor_sync(0xFFFFFFFFu, A2a, 16));
    A2b = add2(A2b, __shfl_xor_sync(0xFFFFFFFFu, A2b, 16));
    A3a = add2(A3a, __shfl_xor_sync(0xFFFFFFFFu, A3a, 16));
    A3b = add2(A3b, __shfl_xor_sync(0xFFFFFFFFu, A3b, 16));

    // h=0 stores voxels 0,1; h=1 stores voxels 2,3
    unsigned long long s0a = h ? A2a : A0a, s0b = h ? A2b : A0b;
    unsigned long long s1a = h ? A3a : A1a, s1b = h ? A3b : A1b;
    float2 r0 = unpack2(s0a), r1 = unpack2(s0b);
    float2 r2 = unpack2(s1a), r3 = unpack2(s1b);
    float4 oA, oB;
    oA.x = fmaxf(r0.x, 0.f) * CONVEY;
    oA.y = fmaxf(r0.y, 0.f) * CONVEY;
    oA.z = fmaxf(r1.x, 0.f) * CONVEY;
    oA.w = fmaxf(r1.y, 0.f) * CONVEY;
    oB.x = fmaxf(r2.x, 0.f) * CONVEY;
    oB.y = fmaxf(r2.y, 0.f) * CONVEY;
    oB.z = fmaxf(r3.x, 0.f) * CONVEY;
    oB.w = fmaxf(r3.y, 0.f) * CONVEY;
    size_t obase = ((size_t)z * HH + (y0 + ty)) * WW + (x0 + 4 * qx) + 2 * h;
    dst[obase]     = oA;
    dst[obase + 1] = oB;
}

// ---------------- kernel 3: bias-initialize accumulators (every launch!) ------
__global__ void __launch_bounds__(256) k_init_acc(const float* __restrict__ b1,
                                                  const float* __restrict__ b2) {
    int i = blockIdx.x * 256 + threadIdx.x;
    if (i < NB * N1) g_acc1[i] = b1[i & (N1 - 1)];
    if (i < NB * N2) g_acc2[i] = b2[i & (N2 - 1)];
}

// ---------------- kernel 4: FC1 split-K via cp.async deep pipeline ------------
#define KSPLIT  576
#define ROWSPB  176   // 576 * 176 == 101376 exactly
#define GSTAGES 12
__global__ void __launch_bounds__(256) k_gemm1(const float* __restrict__ W1) {
    __shared__ float4 swb[GSTAGES][256];   // 48KB ring
    __shared__ float4 sx[ROWSPB];
    const int f0  = blockIdx.x * ROWSPB;
    const int tid = threadIdx.x;

    if (tid < ROWSPB) sx[tid] = g_neuB[f0 + tid];

    const char* gbase = reinterpret_cast<const char*>(W1)
                      + ((size_t)f0 * N1 + tid * 4) * 4;

    // prologue: stages 0..10 in flight
#pragma unroll
    for (int s = 0; s < GSTAGES - 1; ++s) {
        cp_async16(&swb[s][tid], gbase + (size_t)s * (N1 * 4));
        CP_COMMIT();
    }
    __syncthreads();   // sx visibility

    const int j0 = tid * 4;
    float a00=0,a01=0,a02=0,a03=0;
    float a10=0,a11=0,a12=0,a13=0;
    float a20=0,a21=0,a22=0,a23=0;
    float a30=0,a31=0,a32=0,a33=0;

#pragma unroll 12
    for (int i = 0; i < ROWSPB; ++i) {
        CP_WAIT(GSTAGES - 2);                 // row i ready (own 16B slot)
        float4 w  = swb[i % GSTAGES][tid];
        float4 xv = sx[i];
        a00 += xv.x * w.x; a01 += xv.x * w.y; a02 += xv.x * w.z; a03 += xv.x * w.w;
        a10 += xv.y * w.x; a11 += xv.y * w.y; a12 += xv.y * w.z; a13 += xv.y * w.w;
        a20 += xv.z * w.x; a21 += xv.z * w.y; a22 += xv.z * w.z; a23 += xv.z * w.w;
        a30 += xv.w * w.x; a31 += xv.w * w.y; a32 += xv.w * w.z; a33 += xv.w * w.w;
        if (i + GSTAGES - 1 < ROWSPB)
            cp_async16(&swb[(i + GSTAGES - 1) % GSTAGES][tid],
                       gbase + (size_t)(i + GSTAGES - 1) * (N1 * 4));
        CP_COMMIT();                          // keep group counting aligned
    }

    atomicAdd(&g_acc1[0 * N1 + j0 + 0], a00); atomicAdd(&g_acc1[0 * N1 + j0 + 1], a01);
    atomicAdd(&g_acc1[0 * N1 + j0 + 2], a02); atomicAdd(&g_acc1[0 * N1 + j0 + 3], a03);
    atomicAdd(&g_acc1[1 * N1 + j0 + 0], a10); atomicAdd(&g_acc1[1 * N1 + j0 + 1], a11);
    atomicAdd(&g_acc1[1 * N1 + j0 + 2], a12); atomicAdd(&g_acc1[1 * N1 + j0 + 3], a13);
    atomicAdd(&g_acc1[2 * N1 + j0 + 0], a20); atomicAdd(&g_acc1[2 * N1 + j0 + 1], a21);
    atomicAdd(&g_acc1[2 * N1 + j0 + 2], a22); atomicAdd(&g_acc1[2 * N1 + j0 + 3], a23);
    atomicAdd(&g_acc1[3 * N1 + j0 + 0], a30); atomicAdd(&g_acc1[3 * N1 + j0 + 1], a31);
    atomicAdd(&g_acc1[3 * N1 + j0 + 2], a32); atomicAdd(&g_acc1[3 * N1 + j0 + 3], a33);
}

// ---------------- kernel 5: FC2 (relu(acc1) @ W2), atomics into g_acc2 --------
__global__ void __launch_bounds__(128) k_gemm2(const float* __restrict__ W2) {
    const int t     = threadIdx.x;
    const int jbase = blockIdx.x * 64;
    float acc0 = 0, acc1 = 0, acc2 = 0, acc3 = 0;
#pragma unroll 4
    for (int j = 0; j < 64; ++j) {
        int jj  = jbase + j;
        float w = W2[(size_t)jj * N2 + t];
        acc0 += fmaxf(g_acc1[0 * N1 + jj], 0.f) * w;
        acc1 += fmaxf(g_acc1[1 * N1 + jj], 0.f) * w;
        acc2 += fmaxf(g_acc1[2 * N1 + jj], 0.f) * w;
        acc3 += fmaxf(g_acc1[3 * N1 + jj], 0.f) * w;
    }
    atomicAdd(&g_acc2[0 * N2 + t], acc0);
    atomicAdd(&g_acc2[1 * N2 + t], acc1);
    atomicAdd(&g_acc2[2 * N2 + t], acc2);
    atomicAdd(&g_acc2[3 * N2 + t], acc3);
}

// ---------------- kernel 6: FC3 -> output logits ----------------
__global__ void __launch_bounds__(64) k_fc3(const float* __restrict__ W3,
                                            const float* __restrict__ b3,
                                            float* __restrict__ out) {
    int t = threadIdx.x;
    if (t >= NB * N3) return;
    int b = t / N3, o = t % N3;
    float s = b3[o];
#pragma unroll 8
    for (int k = 0; k < N2; ++k)
        s += fmaxf(g_acc2[b * N2 + k], 0.f) * W3[k * N3 + o];
    out[b * N3 + o] = s;
}

// ---------------- launch ----------------
extern "C" void kernel_launch(void* const* d_in, const int* in_sizes, int n_in,
                              void* d_out, int out_size) {
    const float* vin   = (const float*)d_in[0];
    const float* frame = (const float*)d_in[1];
    const float* syn   = (const float*)d_in[2];
    const float* W1    = (const float*)d_in[3];
    const float* b1    = (const float*)d_in[4];
    const float* W2    = (const float*)d_in[5];
    const float* b2    = (const float*)d_in[6];
    const float* W3    = (const float*)d_in[7];
    const float* b3    = (const float*)d_in[8];
    float* out = (float*)d_out;

    k_init_neu<<<DHW / 256, 256>>>(vin, frame);
    k_transpose<<<NSTEPBLK * 8, 256>>>(syn);

    k_step<<<NSTEPBLK, 128>>>(0);   // A -> B
    k_step<<<NSTEPBLK, 128>>>(1);   // B -> A
    k_step<<<NSTEPBLK, 128>>>(0);   // A -> B
    k_step<<<NSTEPBLK, 128>>>(1);   // B -> A
    k_step<<<NSTEPBLK, 128>>>(0);   // A -> B  (final state in g_neuB)

    k_init_acc<<<18, 256>>>(b1, b2);
    k_gemm1<<<KSPLIT, 256>>>(W1);
    k_gemm2<<<16, 128>>>(W2);
    k_fc3<<<1, 64>>>(W3, b3, out);
}